// round 15
// baseline (speedup 1.0000x reference)
#include <cuda_runtime.h>
#include <cuda_fp16.h>
#include <cstdint>
#include <math.h>

#define B_ 8
#define S_ 2048
#define H_ 256
#define BSROWS (B_*S_)

// ----------------------------- scratch ------------------------------------
__device__ __half g_xh[(size_t)BSROWS * H_];
__device__ __half g_qh[(size_t)BSROWS * H_];
__device__ __half g_kh[(size_t)BSROWS * H_];
__device__ __half g_vh[(size_t)BSROWS * H_];
__device__ __half g_wh[3 * H_ * H_];
__device__ float2 g_cs[S_ * (H_ / 2)];

// ----------------------------- PTX helpers --------------------------------
__device__ __forceinline__ uint32_t smem_u32(const void* p) {
    uint32_t a;
    asm("{ .reg .u64 t; cvta.to.shared.u64 t, %1; cvt.u32.u64 %0, t; }" : "=r"(a) : "l"(p));
    return a;
}
#define CP16(dst, src) asm volatile("cp.async.cg.shared.global [%0], [%1], 16;" :: "r"(dst), "l"(src))
#define CP_COMMIT()    asm volatile("cp.async.commit_group;" ::: "memory")
#define CP_WAIT(n)     asm volatile("cp.async.wait_group %0;" :: "n"(n) : "memory")
#define PAIR_BAR(id)   asm volatile("bar.sync %0, 64;" :: "r"((id) + 1) : "memory")

__device__ __forceinline__ void ldm_x4(uint32_t& r0, uint32_t& r1, uint32_t& r2,
                                       uint32_t& r3, uint32_t addr) {
    asm volatile("ldmatrix.sync.aligned.m8n8.x4.shared.b16 {%0,%1,%2,%3}, [%4];"
                 : "=r"(r0), "=r"(r1), "=r"(r2), "=r"(r3) : "r"(addr));
}
__device__ __forceinline__ void ldm_x4t(uint32_t& r0, uint32_t& r1, uint32_t& r2,
                                        uint32_t& r3, uint32_t addr) {
    asm volatile("ldmatrix.sync.aligned.m8n8.x4.trans.shared.b16 {%0,%1,%2,%3}, [%4];"
                 : "=r"(r0), "=r"(r1), "=r"(r2), "=r"(r3) : "r"(addr));
}
__device__ __forceinline__ void hmma(float* c, uint32_t a0, uint32_t a1, uint32_t a2,
                                     uint32_t a3, uint32_t b0, uint32_t b1) {
    asm volatile(
        "mma.sync.aligned.m16n8k16.row.col.f32.f16.f16.f32 "
        "{%0,%1,%2,%3}, {%4,%5,%6,%7}, {%8,%9}, {%0,%1,%2,%3};"
        : "+f"(c[0]), "+f"(c[1]), "+f"(c[2]), "+f"(c[3])
        : "r"(a0), "r"(a1), "r"(a2), "r"(a3), "r"(b0), "r"(b1));
}

// ----------------------------- prep (fused) --------------------------------
__global__ __launch_bounds__(256) void prep_kernel(
    const float* __restrict__ x, const float* __restrict__ wq,
    const float* __restrict__ wk, const float* __restrict__ wv)
{
    const int bid = blockIdx.x, tid = threadIdx.x;
    if (bid < 128) {
        int i = tid & 127;
        double e = -2.0 * ((double)i - 1.0) / 256.0;
        float theta = (float)exp(e * 9.210340371976184);   // ln(10000)
        int p0 = bid * 16 + (tid >> 7) * 8;
        #pragma unroll
        for (int p = 0; p < 8; p++) {
            int pos = p0 + p;
            float ang = __fmul_rn((float)pos, theta);
            float sv, cv;
            sincosf(ang, &sv, &cv);
            g_cs[pos * 128 + i] = make_float2(cv, sv);
        }
    } else if (bid < 320) {
        int zi = bid - 128;
        int z = zi >> 6;
        int i = (zi & 63) * 256 + tid;
        const float* w = (z == 0) ? wq : (z == 1) ? wk : wv;
        float4 v = ((const float4*)w)[i];
        __half2* dst = (__half2*)(g_wh + (size_t)z * H_ * H_);
        dst[2 * i]     = __floats2half2_rn(v.x, v.y);
        dst[2 * i + 1] = __floats2half2_rn(v.z, v.w);
    } else {
        int i = (bid - 320) * 256 + tid;
        float4 v = ((const float4*)x)[i];
        ((__half2*)g_xh)[2 * i]     = __floats2half2_rn(v.x, v.y);
        ((__half2*)g_xh)[2 * i + 1] = __floats2half2_rn(v.z, v.w);
    }
}

// ----------------------------- proj (HMMA, A-resident, 2 CTA/SM) -----------
// CTA 128(M) x 128(N), 256 thr. A [128x256] fp16 resident in smem (64KB,
// loaded once). B streamed as 12 chunks (3z x 4kc of 64K) of 16KB, double-
// buffered (32KB). 96KB/CTA -> 2 CTAs/SM, 256 CTAs co-resident. L2 fill
// demand ~5.5TB/s, under the LTS ceiling, so chunk loads hide fully.
#define PRJ_SMEM 98304
#define PJA_ 0u
#define PJB_ 65536u
__global__ __launch_bounds__(256, 2) void proj_kernel() {
    extern __shared__ char sm[];
    uint32_t sb = smem_u32(sm);
    const int tid = threadIdx.x, lane = tid & 31, w = tid >> 5;
    const int wm = w >> 1, wn = w & 1;
    const int m0 = blockIdx.x * 128, n0g = blockIdx.y * 128;

    auto load_B = [&](int t, int buf) {          // 16KB: 128 n-rows x 64 K
        int z = t >> 2, kc = t & 3;
        const __half* wsrc = g_wh + (size_t)z * H_ * H_;
        uint32_t base = sb + PJB_ + buf * 16384;
        #pragma unroll
        for (int i = tid; i < 1024; i += 256) {
            int row = i >> 3, g = i & 7;
            uint32_t sw = row * 128 + ((g ^ (row & 7)) << 4);
            CP16(base + sw, wsrc + (((size_t)(n0g + row)) << 8) + kc * 64 + g * 8);
        }
    };

    // A full tile (group 1) then B chunk 0 (group 2)
    for (int i = tid; i < 4096; i += 256) {
        int row = i >> 5, g = i & 31;
        uint32_t sw = row * 512 + ((g ^ (row & 7)) << 4);
        CP16(sb + PJA_ + sw, g_xh + (((size_t)(m0 + row)) << 8) + g * 8);
    }
    CP_COMMIT();
    load_B(0, 0);
    CP_COMMIT();

    float O[2][8][4];
    #pragma unroll
    for (int mi = 0; mi < 2; mi++)
        #pragma unroll
        for (int j = 0; j < 8; j++)
            #pragma unroll
            for (int c = 0; c < 4; c++) O[mi][j][c] = 0.f;

    #pragma unroll 1
    for (int t = 0; t < 12; t++) {
        const int cur = t & 1;
        const int kc = t & 3;
        if (t + 1 < 12) { load_B(t + 1, cur ^ 1); CP_COMMIT(); }
        if (t + 1 < 12) CP_WAIT(1); else CP_WAIT(0);
        __syncthreads();                        // A + B chunk t visible

        const uint32_t bBase = sb + PJB_ + cur * 16384;
        #pragma unroll
        for (int ks = 0; ks < 4; ks++) {
            uint32_t A[2][4];
            #pragma unroll
            for (int mi = 0; mi < 2; mi++) {
                uint32_t aRow = wm * 32 + mi * 16 + (lane & 15);
                uint32_t g = kc * 8 + ks * 2 + (lane >> 4);
                ldm_x4(A[mi][0], A[mi][1], A[mi][2], A[mi][3],
                       sb + PJA_ + aRow * 512 + ((g ^ (aRow & 7)) << 4));
            }
            #pragma unroll
            for (int nb = 0; nb < 4; nb++) {
                uint32_t nrow = wn * 64 + nb * 16 + (lane & 7) + ((lane >> 4) << 3);
                uint32_t g = ks * 2 + ((lane >> 3) & 1);
                uint32_t b0, b1, b2, b3;
                ldm_x4(b0, b1, b2, b3, bBase + nrow * 128 + ((g ^ (nrow & 7)) << 4));
                #pragma unroll
                for (int mi = 0; mi < 2; mi++) {
                    hmma(O[mi][2 * nb],     A[mi][0], A[mi][1], A[mi][2], A[mi][3], b0, b1);
                    hmma(O[mi][2 * nb + 1], A[mi][0], A[mi][1], A[mi][2], A[mi][3], b2, b3);
                }
            }
        }

        // z boundary: epilogue (RoPE for z<2), reset accumulators
        if ((t & 3) == 3) {
            const int z = t >> 2;
            __half* outp = (z == 0) ? g_qh : (z == 1) ? g_kh : g_vh;
            #pragma unroll
            for (int mi = 0; mi < 2; mi++) {
                int r0 = m0 + wm * 32 + mi * 16 + (lane >> 2), r1 = r0 + 8;
                int pos0 = r0 & (S_ - 1), pos1 = r1 & (S_ - 1);
                #pragma unroll
                for (int j = 0; j < 8; j++) {
                    int col = n0g + wn * 64 + j * 8 + (lane & 3) * 2;
                    if (z < 2) {
                        float2 cs0 = g_cs[pos0 * 128 + (col >> 1)];
                        float2 cs1 = g_cs[pos1 * 128 + (col >> 1)];
                        *(__half2*)(outp + (((size_t)r0) << 8) + col) =
                            __floats2half2_rn(cs0.x * O[mi][j][0] + cs0.y * O[mi][j][1],
                                              -cs0.y * O[mi][j][0] + cs0.x * O[mi][j][1]);
                        *(__half2*)(outp + (((size_t)r1) << 8) + col) =
                            __floats2half2_rn(cs1.x * O[mi][j][2] + cs1.y * O[mi][j][3],
                                              -cs1.y * O[mi][j][2] + cs1.x * O[mi][j][3]);
                    } else {
                        *(__half2*)(outp + (((size_t)r0) << 8) + col) =
                            __floats2half2_rn(O[mi][j][0], O[mi][j][1]);
                        *(__half2*)(outp + (((size_t)r1) << 8) + col) =
                            __floats2half2_rn(O[mi][j][2], O[mi][j][3]);
                    }
                    #pragma unroll
                    for (int c = 0; c < 4; c++) O[mi][j][c] = 0.f;
                }
            }
        }
        __syncthreads();                        // buf cur free before t+2 load
    }
}

// ----------------------------- flash (HMMA) --------------------------------
// At the mma.sync issue roofline (256 HMMA/SMSP/iter x rt12 = measured iter).
// 18 groups x 8 batches = 144 CTAs: 4 singletons (qt 31..28) + 14 pairs.
#define SQ_ 0
#define SK_ 32768
#define SV_ (32768*3)
#define SP_ (32768*5)
#define SLI_ (32768*5 + 9216)
#define FL_SMEM (32768*5 + 9216 + 512)
#define SCALE2 0.0901684400054f   /* log2(e)/16 */

__global__ __launch_bounds__(256, 1) void flash_kernel(float* __restrict__ out) {
    extern __shared__ char sm[];
    uint32_t sb = smem_u32(sm);
    float* liS = (float*)(sm + SLI_);
    const int tid = threadIdx.x, lane = tid & 31, w = tid >> 5;
    const int rg = w >> 1, ch = w & 1;
    const int b = blockIdx.y, g9 = blockIdx.x;

    int tiles[2], nt;
    if (g9 < 4) { tiles[0] = 31 - g9; tiles[1] = 0; nt = 1; }
    else        { tiles[0] = 27 - (g9 - 4); tiles[1] = g9 - 4; nt = 2; }

    for (int ti = 0; ti < nt; ti++) {
        const int qt = tiles[ti];
        const int q0 = qt * 64, nkt = qt + 1;
        __syncthreads();

        for (int i = tid; i < 2048; i += 256) {
            int row = i >> 5, gg = i & 31;
            uint32_t sw = row * 512 + ((gg ^ (row & 7)) << 4);
            CP16(sb + SQ_ + sw, g_qh + (((size_t)(b * S_ + q0 + row)) << 8) + gg * 8);
            size_t go = (((size_t)(b * S_ + row)) << 8) + gg * 8;
            CP16(sb + SK_ + sw, g_kh + go);
            CP16(sb + SV_ + sw, g_vh + go);
        }
        CP_COMMIT();
        CP_WAIT(0);
        __syncthreads();

        uint32_t Qf[16][4];
        {
            const uint32_t aRow = rg * 16 + (lane & 15);
            const uint32_t aQbase = sb + SQ_ + aRow * 512;
            const int aSel = lane >> 4, aXor = aRow & 7;
            #pragma unroll
            for (int ks = 0; ks < 16; ks++)
                ldm_x4(Qf[ks][0], Qf[ks][1], Qf[ks][2], Qf[ks][3],
                       aQbase + (((ks * 2 + aSel) ^ aXor) << 4));
        }

        float O[16][4];
        #pragma unroll
        for (int j = 0; j < 16; j++)
            #pragma unroll
            for (int c = 0; c < 4; c++) O[j][c] = 0.f;
        float li0 = 0.f, li1 = 0.f;
        const int aSel = lane >> 4;

        for (int kt = 0; kt < nkt; kt++) {
            const int cur = kt & 1;
            if (kt > 0) {
                CP_WAIT(0);
                __syncthreads();
            }
            if (kt + 1 < nkt) {
                int nb = (kt + 1) & 1, k0n = (kt + 1) * 64;
                for (int i = tid; i < 2048; i += 256) {
                    int row = i >> 5, gg = i & 31;
                    uint32_t sw = row * 512 + ((gg ^ (row & 7)) << 4);
                    size_t go = (((size_t)(b * S_ + k0n + row)) << 8) + gg * 8;
                    CP16(sb + SK_ + nb * 32768 + sw, g_kh + go);
                    CP16(sb + SV_ + nb * 32768 + sw, g_vh + go);
                }
                CP_COMMIT();
            }

            // ---- QK^T ----
            float S4[4][4];
            #pragma unroll
            for (int j = 0; j < 4; j++)
                #pragma unroll
                for (int c = 0; c < 4; c++) S4[j][c] = 0.f;

            const uint32_t kBase = sb + SK_ + cur * 32768;
            #pragma unroll
            for (int ks = 0; ks < 16; ks++) {
                #pragma unroll
                for (int nblk = 0; nblk < 2; nblk++) {
                    uint32_t nrow = ch * 32 + nblk * 16 + (lane & 7) + ((lane >> 4) << 3);
                    uint32_t gg = ks * 2 + ((lane >> 3) & 1);
                    uint32_t b0, b1, b2, b3;
                    ldm_x4(b0, b1, b2, b3, kBase + nrow * 512 + ((gg ^ (nrow & 7)) << 4));
                    hmma(S4[2 * nblk],     Qf[ks][0], Qf[ks][1], Qf[ks][2], Qf[ks][3], b0, b1);
                    hmma(S4[2 * nblk + 1], Qf[ks][0], Qf[ks][1], Qf[ks][2], Qf[ks][3], b2, b3);
                }
            }

            // ---- softmax chunk ----
            {
                const int row0 = q0 + rg * 16 + (lane >> 2);
                const int colb = kt * 64 + ch * 32 + (lane & 3) * 2;
                const bool diag = (kt == qt);
                uint32_t pb = SP_ + (rg * 16 + (lane >> 2)) * 144 +
                              (ch * 32 + (lane & 3) * 2) * 2;
                #pragma unroll
                for (int cnk = 0; cnk < 4; cnk++) {
                    int c0 = colb + cnk * 8;
                    float p00 = exp2f(S4[cnk][0] * SCALE2);
                    float p01 = exp2f(S4[cnk][1] * SCALE2);
                    float p10 = exp2f(S4[cnk][2] * SCALE2);
                    float p11 = exp2f(S4[cnk][3] * SCALE2);
                    if (diag) {
                        if (c0     > row0) p00 = 0.f;
                        if (c0 + 1 > row0) p01 = 0.f;
                        if (c0     > row0 + 8) p10 = 0.f;
                        if (c0 + 1 > row0 + 8) p11 = 0.f;
                    }
                    li0 += p00 + p01;
                    li1 += p10 + p11;
                    *(__half2*)(sm + pb + cnk * 16)           = __floats2half2_rn(p00, p01);
                    *(__half2*)(sm + pb + cnk * 16 + 8 * 144) = __floats2half2_rn(p10, p11);
                }
            }
            PAIR_BAR(rg);

            // ---- PV ----
            const uint32_t vBase = sb + SV_ + cur * 32768;
            const uint32_t pBase = sb + SP_ + (rg * 16 + (lane & 15)) * 144;
            #pragma unroll
            for (int kc = 0; kc < 4; kc++) {
                uint32_t a0, a1, a2, a3;
                ldm_x4(a0, a1, a2, a3, pBase + ((kc * 2 + aSel) << 4));
                #pragma unroll
                for (int nb = 0; nb < 8; nb++) {
                    uint32_t n0v = ch * 128 + nb * 16;
                    uint32_t krow = kc * 16 + (lane & 7) + (((lane >> 3) & 1) << 3);
                    uint32_t gg = (n0v >> 3) + (lane >> 4);
                    uint32_t b0, b1, b2, b3;
                    ldm_x4t(b0, b1, b2, b3, vBase + krow * 512 + ((gg ^ (krow & 7)) << 4));
                    hmma(O[2 * nb],     a0, a1, a2, a3, b0, b1);
                    hmma(O[2 * nb + 1], a0, a1, a2, a3, b2, b3);
                }
            }
            PAIR_BAR(rg);
        }

        // ---- normalize + store ----
        li0 += __shfl_xor_sync(0xffffffffu, li0, 1);
        li0 += __shfl_xor_sync(0xffffffffu, li0, 2);
        li1 += __shfl_xor_sync(0xffffffffu, li1, 1);
        li1 += __shfl_xor_sync(0xffffffffu, li1, 2);
        int lrow = rg * 16 + (lane >> 2);
        liS[ch * 64 + lrow]     = li0;
        liS[ch * 64 + lrow + 8] = li1;
        PAIR_BAR(rg);
        float inv0 = 1.0f / (liS[lrow] + liS[64 + lrow]);
        float inv1 = 1.0f / (liS[lrow + 8] + liS[64 + lrow + 8]);

        float* dst0 = out + (((size_t)(b * S_ + q0 + lrow)) << 8);
        float* dst1 = dst0 + (8 << 8);
        #pragma unroll
        for (int j = 0; j < 16; j++) {
            int col = ch * 128 + j * 8 + (lane & 3) * 2;
            *(float2*)(dst0 + col) = make_float2(O[j][0] * inv0, O[j][1] * inv0);
            *(float2*)(dst1 + col) = make_float2(O[j][2] * inv1, O[j][3] * inv1);
        }
    }
}

// ---------------------------------------------------------------------------
extern "C" void kernel_launch(void* const* d_in, const int* in_sizes, int n_in,
                              void* d_out, int out_size) {
    const float* x  = (const float*)d_in[0];
    const float* wq = (const float*)d_in[1];
    const float* wk = (const float*)d_in[2];
    const float* wv = (const float*)d_in[3];
    float* out = (float*)d_out;

    cudaFuncSetAttribute(proj_kernel,  cudaFuncAttributeMaxDynamicSharedMemorySize, PRJ_SMEM);
    cudaFuncSetAttribute(flash_kernel, cudaFuncAttributeMaxDynamicSharedMemorySize, FL_SMEM);

    prep_kernel<<<4416, 256>>>(x, wq, wk, wv);
    proj_kernel<<<dim3(128, 2), 256, PRJ_SMEM>>>();
    flash_kernel<<<dim3(18, B_), 256, FL_SMEM>>>(out);
}

// round 16
// speedup vs baseline: 1.0228x; 1.0228x over previous
#include <cuda_runtime.h>
#include <cuda_fp16.h>
#include <cstdint>
#include <math.h>

#define B_ 8
#define S_ 2048
#define H_ 256
#define BSROWS (B_*S_)

// ----------------------------- scratch ------------------------------------
__device__ __half g_xh[(size_t)BSROWS * H_];
__device__ __half g_qh[(size_t)BSROWS * H_];
__device__ __half g_kh[(size_t)BSROWS * H_];
__device__ __half g_vh[(size_t)BSROWS * H_];
__device__ __half g_wh[3 * H_ * H_];
__device__ float2 g_cs[S_ * (H_ / 2)];

// ----------------------------- PTX helpers --------------------------------
__device__ __forceinline__ uint32_t smem_u32(const void* p) {
    uint32_t a;
    asm("{ .reg .u64 t; cvta.to.shared.u64 t, %1; cvt.u32.u64 %0, t; }" : "=r"(a) : "l"(p));
    return a;
}
#define CP16(dst, src) asm volatile("cp.async.cg.shared.global [%0], [%1], 16;" :: "r"(dst), "l"(src))
#define CP_COMMIT()    asm volatile("cp.async.commit_group;" ::: "memory")
#define CP_WAIT(n)     asm volatile("cp.async.wait_group %0;" :: "n"(n) : "memory")
#define PAIR_BAR(id)   asm volatile("bar.sync %0, 64;" :: "r"((id) + 1) : "memory")

__device__ __forceinline__ void ldm_x4(uint32_t& r0, uint32_t& r1, uint32_t& r2,
                                       uint32_t& r3, uint32_t addr) {
    asm volatile("ldmatrix.sync.aligned.m8n8.x4.shared.b16 {%0,%1,%2,%3}, [%4];"
                 : "=r"(r0), "=r"(r1), "=r"(r2), "=r"(r3) : "r"(addr));
}
__device__ __forceinline__ void ldm_x4t(uint32_t& r0, uint32_t& r1, uint32_t& r2,
                                        uint32_t& r3, uint32_t addr) {
    asm volatile("ldmatrix.sync.aligned.m8n8.x4.trans.shared.b16 {%0,%1,%2,%3}, [%4];"
                 : "=r"(r0), "=r"(r1), "=r"(r2), "=r"(r3) : "r"(addr));
}
__device__ __forceinline__ void hmma(float* c, uint32_t a0, uint32_t a1, uint32_t a2,
                                     uint32_t a3, uint32_t b0, uint32_t b1) {
    asm volatile(
        "mma.sync.aligned.m16n8k16.row.col.f32.f16.f16.f32 "
        "{%0,%1,%2,%3}, {%4,%5,%6,%7}, {%8,%9}, {%0,%1,%2,%3};"
        : "+f"(c[0]), "+f"(c[1]), "+f"(c[2]), "+f"(c[3])
        : "r"(a0), "r"(a1), "r"(a2), "r"(a3), "r"(b0), "r"(b1));
}

// ----------------------------- prep (fused) --------------------------------
__global__ __launch_bounds__(256) void prep_kernel(
    const float* __restrict__ x, const float* __restrict__ wq,
    const float* __restrict__ wk, const float* __restrict__ wv)
{
    const int bid = blockIdx.x, tid = threadIdx.x;
    if (bid < 128) {
        int i = tid & 127;
        double e = -2.0 * ((double)i - 1.0) / 256.0;
        float theta = (float)exp(e * 9.210340371976184);   // ln(10000)
        int p0 = bid * 16 + (tid >> 7) * 8;
        #pragma unroll
        for (int p = 0; p < 8; p++) {
            int pos = p0 + p;
            float ang = __fmul_rn((float)pos, theta);
            float sv, cv;
            sincosf(ang, &sv, &cv);
            g_cs[pos * 128 + i] = make_float2(cv, sv);
        }
    } else if (bid < 320) {
        int zi = bid - 128;
        int z = zi >> 6;
        int i = (zi & 63) * 256 + tid;
        const float* w = (z == 0) ? wq : (z == 1) ? wk : wv;
        float4 v = ((const float4*)w)[i];
        __half2* dst = (__half2*)(g_wh + (size_t)z * H_ * H_);
        dst[2 * i]     = __floats2half2_rn(v.x, v.y);
        dst[2 * i + 1] = __floats2half2_rn(v.z, v.w);
    } else {
        int i = (bid - 320) * 256 + tid;
        float4 v = ((const float4*)x)[i];
        ((__half2*)g_xh)[2 * i]     = __floats2half2_rn(v.x, v.y);
        ((__half2*)g_xh)[2 * i + 1] = __floats2half2_rn(v.z, v.w);
    }
}

// ----------------------------- proj (HMMA, 2 CTA/SM) -- round-14 exact -----
// CTA tile 128(M) x 128(N), 256 thr. K streamed as 12 chunks (3z x 4kc of 64):
// A 16KB + B 16KB per chunk, double-buffered -> 64KB smem, 2 CTAs/SM.
#define PRJ_SMEM 65536
__global__ __launch_bounds__(256, 2) void proj_kernel() {
    extern __shared__ char sm[];
    uint32_t sb = smem_u32(sm);
    const int tid = threadIdx.x, lane = tid & 31, w = tid >> 5;
    const int wm = w >> 1, wn = w & 1;
    const int m0 = blockIdx.x * 128, n0g = blockIdx.y * 128;

    auto load_chunk = [&](int t, int buf) {
        int z = t >> 2, kc = t & 3;
        const __half* wsrc = g_wh + (size_t)z * H_ * H_;
        uint32_t base = sb + buf * 32768;
        #pragma unroll
        for (int i = tid; i < 1024; i += 256) {
            int row = i >> 3, g = i & 7;
            uint32_t sw = row * 128 + ((g ^ (row & 7)) << 4);
            CP16(base + sw,
                 g_xh + (((size_t)(m0 + row)) << 8) + kc * 64 + g * 8);
            CP16(base + 16384 + sw,
                 wsrc + (((size_t)(n0g + row)) << 8) + kc * 64 + g * 8);
        }
    };

    load_chunk(0, 0);
    CP_COMMIT();

    float O[2][8][4];
    #pragma unroll
    for (int mi = 0; mi < 2; mi++)
        #pragma unroll
        for (int j = 0; j < 8; j++)
            #pragma unroll
            for (int c = 0; c < 4; c++) O[mi][j][c] = 0.f;

    #pragma unroll 1
    for (int t = 0; t < 12; t++) {
        const int cur = t & 1;
        if (t + 1 < 12) { load_chunk(t + 1, cur ^ 1); CP_COMMIT(); }
        if (t + 1 < 12) CP_WAIT(1); else CP_WAIT(0);
        __syncthreads();                        // chunk t visible

        const uint32_t aBase = sb + cur * 32768;
        const uint32_t bBase = aBase + 16384;
        #pragma unroll
        for (int ks = 0; ks < 4; ks++) {
            uint32_t A[2][4];
            #pragma unroll
            for (int mi = 0; mi < 2; mi++) {
                uint32_t aRow = wm * 32 + mi * 16 + (lane & 15);
                uint32_t g = ks * 2 + (lane >> 4);
                ldm_x4(A[mi][0], A[mi][1], A[mi][2], A[mi][3],
                       aBase + aRow * 128 + ((g ^ (aRow & 7)) << 4));
            }
            #pragma unroll
            for (int nb = 0; nb < 4; nb++) {
                uint32_t nrow = wn * 64 + nb * 16 + (lane & 7) + ((lane >> 4) << 3);
                uint32_t g = ks * 2 + ((lane >> 3) & 1);
                uint32_t b0, b1, b2, b3;
                ldm_x4(b0, b1, b2, b3, bBase + nrow * 128 + ((g ^ (nrow & 7)) << 4));
                #pragma unroll
                for (int mi = 0; mi < 2; mi++) {
                    hmma(O[mi][2 * nb],     A[mi][0], A[mi][1], A[mi][2], A[mi][3], b0, b1);
                    hmma(O[mi][2 * nb + 1], A[mi][0], A[mi][1], A[mi][2], A[mi][3], b2, b3);
                }
            }
        }

        if ((t & 3) == 3) {
            const int z = t >> 2;
            __half* outp = (z == 0) ? g_qh : (z == 1) ? g_kh : g_vh;
            #pragma unroll
            for (int mi = 0; mi < 2; mi++) {
                int r0 = m0 + wm * 32 + mi * 16 + (lane >> 2), r1 = r0 + 8;
                int pos0 = r0 & (S_ - 1), pos1 = r1 & (S_ - 1);
                #pragma unroll
                for (int j = 0; j < 8; j++) {
                    int col = n0g + wn * 64 + j * 8 + (lane & 3) * 2;
                    if (z < 2) {
                        float2 cs0 = g_cs[pos0 * 128 + (col >> 1)];
                        float2 cs1 = g_cs[pos1 * 128 + (col >> 1)];
                        *(__half2*)(outp + (((size_t)r0) << 8) + col) =
                            __floats2half2_rn(cs0.x * O[mi][j][0] + cs0.y * O[mi][j][1],
                                              -cs0.y * O[mi][j][0] + cs0.x * O[mi][j][1]);
                        *(__half2*)(outp + (((size_t)r1) << 8) + col) =
                            __floats2half2_rn(cs1.x * O[mi][j][2] + cs1.y * O[mi][j][3],
                                              -cs1.y * O[mi][j][2] + cs1.x * O[mi][j][3]);
                    } else {
                        *(__half2*)(outp + (((size_t)r0) << 8) + col) =
                            __floats2half2_rn(O[mi][j][0], O[mi][j][1]);
                        *(__half2*)(outp + (((size_t)r1) << 8) + col) =
                            __floats2half2_rn(O[mi][j][2], O[mi][j][3]);
                    }
                    #pragma unroll
                    for (int c = 0; c < 4; c++) O[mi][j][c] = 0.f;
                }
            }
        }
        __syncthreads();                        // buf cur free for t+2's load
    }
}

// ----------------------------- flash (HMMA) --------------------------------
// 18 groups x 8 batches = 144 CTAs (4 singletons qt31..28 + 14 pairs p,27-p).
// Cross-tile prefetch: during a tile's LAST iteration, the next tile's Q
// (SQ_ is dead after the Qf hoist) and K/V tile0 (opposite parity buffer,
// tracked by a running base) are prefetched under the final HMMA + epilogue.
#define SQ_ 0
#define SK_ 32768
#define SV_ (32768*3)
#define SP_ (32768*5)
#define SLI_ (32768*5 + 9216)
#define FL_SMEM (32768*5 + 9216 + 512)
#define SCALE2 0.0901684400054f   /* log2(e)/16 */

__global__ __launch_bounds__(256, 1) void flash_kernel(float* __restrict__ out) {
    extern __shared__ char sm[];
    uint32_t sb = smem_u32(sm);
    float* liS = (float*)(sm + SLI_);
    const int tid = threadIdx.x, lane = tid & 31, w = tid >> 5;
    const int rg = w >> 1, ch = w & 1;
    const int b = blockIdx.y, g9 = blockIdx.x;

    int tiles[2], nt;
    if (g9 < 4) { tiles[0] = 31 - g9; tiles[1] = 0; nt = 1; }
    else        { tiles[0] = 27 - (g9 - 4); tiles[1] = g9 - 4; nt = 2; }

    auto load_Q = [&](int qt) {
        for (int i = tid; i < 2048; i += 256) {
            int row = i >> 5, gg = i & 31;
            uint32_t sw = row * 512 + ((gg ^ (row & 7)) << 4);
            CP16(sb + SQ_ + sw,
                 g_qh + (((size_t)(b * S_ + qt * 64 + row)) << 8) + gg * 8);
        }
    };
    auto load_KV = [&](int kt, int buf) {
        for (int i = tid; i < 2048; i += 256) {
            int row = i >> 5, gg = i & 31;
            uint32_t sw = row * 512 + ((gg ^ (row & 7)) << 4);
            size_t go = (((size_t)(b * S_ + kt * 64 + row)) << 8) + gg * 8;
            CP16(sb + SK_ + buf * 32768 + sw, g_kh + go);
            CP16(sb + SV_ + buf * 32768 + sw, g_vh + go);
        }
    };

    int base = 0;                        // K/V buffer parity base, carried

    for (int ti = 0; ti < nt; ti++) {
        const int qt = tiles[ti];
        const int q0 = qt * 64, nkt = qt + 1;

        if (ti == 0) {
            load_Q(qt);
            load_KV(0, base & 1);
            CP_COMMIT();
        }
        // (ti>0: Q + KV0 already prefetched during previous tile's last iter)
        CP_WAIT(0);
        __syncthreads();

        uint32_t Qf[16][4];
        {
            const uint32_t aRow = rg * 16 + (lane & 15);
            const uint32_t aQbase = sb + SQ_ + aRow * 512;
            const int aSel = lane >> 4, aXor = aRow & 7;
            #pragma unroll
            for (int ks = 0; ks < 16; ks++)
                ldm_x4(Qf[ks][0], Qf[ks][1], Qf[ks][2], Qf[ks][3],
                       aQbase + (((ks * 2 + aSel) ^ aXor) << 4));
        }

        float O[16][4];
        #pragma unroll
        for (int j = 0; j < 16; j++)
            #pragma unroll
            for (int c = 0; c < 4; c++) O[j][c] = 0.f;
        float li0 = 0.f, li1 = 0.f;
        const int aSel = lane >> 4;

        for (int kt = 0; kt < nkt; kt++) {
            const int cur = (base + kt) & 1;
            if (kt > 0) {
                CP_WAIT(0);
                __syncthreads();
            }
            if (kt + 1 < nkt) {
                load_KV(kt + 1, (base + kt + 1) & 1);
                CP_COMMIT();
            } else if (ti + 1 < nt) {
                // cross-tile prefetch: Q smem dead (Qf in regs), other buf free
                load_Q(tiles[ti + 1]);
                load_KV(0, (base + nkt) & 1);
                CP_COMMIT();
            }

            // ---- QK^T ----
            float S4[4][4];
            #pragma unroll
            for (int j = 0; j < 4; j++)
                #pragma unroll
                for (int c = 0; c < 4; c++) S4[j][c] = 0.f;

            const uint32_t kBase = sb + SK_ + cur * 32768;
            #pragma unroll
            for (int ks = 0; ks < 16; ks++) {
                #pragma unroll
                for (int nblk = 0; nblk < 2; nblk++) {
                    uint32_t nrow = ch * 32 + nblk * 16 + (lane & 7) + ((lane >> 4) << 3);
                    uint32_t gg = ks * 2 + ((lane >> 3) & 1);
                    uint32_t b0, b1, b2, b3;
                    ldm_x4(b0, b1, b2, b3, kBase + nrow * 512 + ((gg ^ (nrow & 7)) << 4));
                    hmma(S4[2 * nblk],     Qf[ks][0], Qf[ks][1], Qf[ks][2], Qf[ks][3], b0, b1);
                    hmma(S4[2 * nblk + 1], Qf[ks][0], Qf[ks][1], Qf[ks][2], Qf[ks][3], b2, b3);
                }
            }

            // ---- softmax chunk ----
            {
                const int row0 = q0 + rg * 16 + (lane >> 2);
                const int colb = kt * 64 + ch * 32 + (lane & 3) * 2;
                const bool diag = (kt == qt);
                uint32_t pb = SP_ + (rg * 16 + (lane >> 2)) * 144 +
                              (ch * 32 + (lane & 3) * 2) * 2;
                #pragma unroll
                for (int cnk = 0; cnk < 4; cnk++) {
                    int c0 = colb + cnk * 8;
                    float p00 = exp2f(S4[cnk][0] * SCALE2);
                    float p01 = exp2f(S4[cnk][1] * SCALE2);
                    float p10 = exp2f(S4[cnk][2] * SCALE2);
                    float p11 = exp2f(S4[cnk][3] * SCALE2);
                    if (diag) {
                        if (c0     > row0) p00 = 0.f;
                        if (c0 + 1 > row0) p01 = 0.f;
                        if (c0     > row0 + 8) p10 = 0.f;
                        if (c0 + 1 > row0 + 8) p11 = 0.f;
                    }
                    li0 += p00 + p01;
                    li1 += p10 + p11;
                    *(__half2*)(sm + pb + cnk * 16)           = __floats2half2_rn(p00, p01);
                    *(__half2*)(sm + pb + cnk * 16 + 8 * 144) = __floats2half2_rn(p10, p11);
                }
            }
            PAIR_BAR(rg);

            // ---- PV ----
            const uint32_t vBase = sb + SV_ + cur * 32768;
            const uint32_t pBase = sb + SP_ + (rg * 16 + (lane & 15)) * 144;
            #pragma unroll
            for (int kc = 0; kc < 4; kc++) {
                uint32_t a0, a1, a2, a3;
                ldm_x4(a0, a1, a2, a3, pBase + ((kc * 2 + aSel) << 4));
                #pragma unroll
                for (int nb = 0; nb < 8; nb++) {
                    uint32_t n0v = ch * 128 + nb * 16;
                    uint32_t krow = kc * 16 + (lane & 7) + (((lane >> 3) & 1) << 3);
                    uint32_t gg = (n0v >> 3) + (lane >> 4);
                    uint32_t b0, b1, b2, b3;
                    ldm_x4t(b0, b1, b2, b3, vBase + krow * 512 + ((gg ^ (krow & 7)) << 4));
                    hmma(O[2 * nb],     a0, a1, a2, a3, b0, b1);
                    hmma(O[2 * nb + 1], a0, a1, a2, a3, b2, b3);
                }
            }
            PAIR_BAR(rg);
        }
        base += nkt;

        // ---- normalize + store ----
        li0 += __shfl_xor_sync(0xffffffffu, li0, 1);
        li0 += __shfl_xor_sync(0xffffffffu, li0, 2);
        li1 += __shfl_xor_sync(0xffffffffu, li1, 1);
        li1 += __shfl_xor_sync(0xffffffffu, li1, 2);
        int lrow = rg * 16 + (lane >> 2);
        liS[ch * 64 + lrow]     = li0;
        liS[ch * 64 + lrow + 8] = li1;
        PAIR_BAR(rg);
        float inv0 = 1.0f / (liS[lrow] + liS[64 + lrow]);
        float inv1 = 1.0f / (liS[lrow + 8] + liS[64 + lrow + 8]);

        float* dst0 = out + (((size_t)(b * S_ + q0 + lrow)) << 8);
        float* dst1 = dst0 + (8 << 8);
        #pragma unroll
        for (int j = 0; j < 16; j++) {
            int col = ch * 128 + j * 8 + (lane & 3) * 2;
            *(float2*)(dst0 + col) = make_float2(O[j][0] * inv0, O[j][1] * inv0);
            *(float2*)(dst1 + col) = make_float2(O[j][2] * inv1, O[j][3] * inv1);
        }
        if (ti + 1 < nt) { PAIR_BAR(rg); }   // liS reads done before reuse
    }
}

// ---------------------------------------------------------------------------
extern "C" void kernel_launch(void* const* d_in, const int* in_sizes, int n_in,
                              void* d_out, int out_size) {
    const float* x  = (const float*)d_in[0];
    const float* wq = (const float*)d_in[1];
    const float* wk = (const float*)d_in[2];
    const float* wv = (const float*)d_in[3];
    float* out = (float*)d_out;

    cudaFuncSetAttribute(proj_kernel,  cudaFuncAttributeMaxDynamicSharedMemorySize, PRJ_SMEM);
    cudaFuncSetAttribute(flash_kernel, cudaFuncAttributeMaxDynamicSharedMemorySize, FL_SMEM);

    prep_kernel<<<4416, 256>>>(x, wq, wk, wv);
    proj_kernel<<<dim3(128, 2), 256, PRJ_SMEM>>>();
    flash_kernel<<<dim3(18, B_), 256, FL_SMEM>>>(out);
}